// round 6
// baseline (speedup 1.0000x reference)
#include <cuda_runtime.h>

#define BATCH 2048
#define TSTEPS 500
#define NIN 64
#define BT (BATCH * TSTEPS)

// 4 MB scratch for per-(b,t) input rowsums (device global: no allocation allowed)
__device__ float g_S[BT];

// evict-first store: output is write-once, never re-read -> keep it out of L2
__device__ __forceinline__ void st_cs4(float* p, float4 v) {
    asm volatile("st.global.cs.v4.f32 [%0], {%1,%2,%3,%4};"
                 :: "l"(p), "f"(v.x), "f"(v.y), "f"(v.z), "f"(v.w) : "memory");
}

// ---------------------------------------------------------------------------
// Kernel 1: rowsum over the N=64 axis. Warp handles 2 rows:
//   lane loads one float4 (32 lanes x 16B = 512B = two 64-float rows),
//   butterfly-reduce within each 16-lane half, lanes 0/16 store.
// Fully coalesced 128B transactions; DRAM-bound by design.
// ---------------------------------------------------------------------------
__global__ void rowsum_kernel(const float* __restrict__ in) {
    unsigned int gtid = blockIdx.x * blockDim.x + threadIdx.x;
    unsigned int warp = gtid >> 5;
    unsigned int lane = gtid & 31;
    unsigned int row0 = warp * 2;
    if (row0 >= BT) return;

    const float4* p = reinterpret_cast<const float4*>(in) + (size_t)warp * 32 + lane;
    float4 v = *p;
    float s = (v.x + v.y) + (v.z + v.w);
    // reduce within 16-lane groups (xor 8,4,2,1 stays inside the half)
    s += __shfl_xor_sync(0xffffffffu, s, 8);
    s += __shfl_xor_sync(0xffffffffu, s, 4);
    s += __shfl_xor_sync(0xffffffffu, s, 2);
    s += __shfl_xor_sync(0xffffffffu, s, 1);
    if ((lane & 15) == 0) g_S[row0 + (lane >> 4)] = s;
}

// ---------------------------------------------------------------------------
// One Euler step of the Izhikevich neuron (matches reference semantics:
// u update uses OLD v; v reset to c on spike; u += d on spike).
// C left-associativity keeps "+I" last, so ptxas schedules the self-dynamics
// prefix off the inter-neuron critical path already.
// ---------------------------------------------------------------------------
__device__ __forceinline__ float izh(float& v, float& u, float I,
                                     float a, float bb, float c, float d) {
    float vn = v + 0.25f * (0.04f * v * v + 5.0f * v + 140.0f - u + I);
    float un = u + 0.25f * a * (bb * v - u);
    bool sp = (vn >= 30.0f);
    float z = sp ? 1.0f : 0.0f;
    v = sp ? c : vn;
    u = un + z * d;
    return z;
}

// ---------------------------------------------------------------------------
// Kernel 2: sequential scan. One thread per batch element, both channels in
// one thread (independent chains -> ILP). S read as float4 per 4 steps;
// scalar [B,T] outputs buffered over 4 steps and flushed as float4;
// [B,T,4] outputs are a native float4 per step. All output stores evict-first.
// ---------------------------------------------------------------------------
__global__ void __launch_bounds__(32, 1)
scan_kernel(const float* __restrict__ w_in, float* __restrict__ out) {
    int b = blockIdx.x * blockDim.x + threadIdx.x;
    if (b >= BATCH) return;

    float w[24];
#pragma unroll
    for (int i = 0; i < 24; i++) w[i] = __ldg(w_in + i);

    // Neuron params (compile-time):
    // LLBN: a=.02 b=.20 c=-65 d=6    v0=-70 u0=-14
    // EBN : a=.02 b=.25 c=-55 d=.05  v0=-64 u0=-16
    // IFN : a=.02 b=.25 c=-65 d=6    v0=-64 u0=-16
    // TN  : a=.02 b=.20 c=-50 d=2    v0=-70 u0=-14
    // MN = IFN
    float vL = -70.f, uL = -14.f, zL = 0.f;
    float vE = -64.f, uE = -16.f;
    float vI = -64.f, uI = -16.f;
    float vT = -70.f, uT = -14.f, zT = 0.f;
    float vM = -64.f, uM = -16.f;
    float vL2 = -70.f, uL2 = -14.f, zL2 = 0.f;
    float vE2 = -64.f, uE2 = -16.f;
    float vI2 = -64.f, uI2 = -16.f;
    float vT2 = -70.f, uT2 = -14.f, zT2 = 0.f;
    float vM2 = -64.f, uM2 = -16.f;

    float* o0 = out;                       // o_spikes  [B,T]
    float* o1 = out + (size_t)BT;          // v         [B,T]
    float* o2 = out + (size_t)2 * BT;      // o_spikes2 [B,T]
    float* o3 = out + (size_t)3 * BT;      // v2        [B,T]
    float* o4 = out + (size_t)4 * BT;      // o_spikes_o [B,T,4]
    float* o5 = out + (size_t)8 * BT;      // v_o        [B,T,4]

    const float4* Sp = reinterpret_cast<const float4*>(&g_S[(size_t)b * TSTEPS]);
    size_t base_bt = (size_t)b * TSTEPS;

    for (int t4 = 0; t4 < TSTEPS; t4 += 4) {
        float4 s4 = Sp[t4 >> 2];
        float a0[4], a1[4], a2[4], a3[4];
#pragma unroll
        for (int j = 0; j < 4; j++) {
            float S = (j == 0) ? s4.x : (j == 1) ? s4.y : (j == 2) ? s4.z : s4.w;
            float zp  = w[0]  * S;
            float zp2 = w[12] * S;

            // --- channel 1 ---
            float z2 = izh(vL, uL, w[2] * (zp * w[1]) + w[3] * zL,
                           0.02f, 0.20f, -65.0f, 6.0f);
            float z3 = izh(vE, uE, zp * w[4] + z2 * w[5],
                           0.02f, 0.25f, -55.0f, 0.05f);
            float z4 = izh(vI, uI, z3 * w[6],
                           0.02f, 0.25f, -65.0f, 6.0f);
            float z5 = izh(vT, uT, w[9] * (z3 * w[8]) + w[10] * zT,
                           0.02f, 0.20f, -50.0f, 2.0f);
            float z6 = izh(vM, uM, z5 * w[11],
                           0.02f, 0.25f, -65.0f, 6.0f);
            zL = z2; zT = z5;

            // --- channel 2 (independent chain: ILP against channel 1) ---
            float z22 = izh(vL2, uL2, w[2] * (zp2 * w[13]) + w[3] * zL2,
                            0.02f, 0.20f, -65.0f, 6.0f);
            float z32 = izh(vE2, uE2, zp2 * w[16] + z22 * w[17],
                            0.02f, 0.25f, -55.0f, 0.05f);
            float z42 = izh(vI2, uI2, z32 * w[18],
                            0.02f, 0.25f, -65.0f, 6.0f);
            float z52 = izh(vT2, uT2, w[9] * (z32 * w[20]) + w[10] * zT2,
                            0.02f, 0.20f, -50.0f, 2.0f);
            float z62 = izh(vM2, uM2, z52 * w[23],
                            0.02f, 0.25f, -65.0f, 6.0f);
            zL2 = z22; zT2 = z52;

            a0[j] = z6;  a1[j] = vM;
            a2[j] = z62; a3[j] = vM2;

            size_t bt4 = (base_bt + (size_t)(t4 + j)) * 4;
            st_cs4(o4 + bt4, make_float4(z2, z3, z4, z5));
            st_cs4(o5 + bt4, make_float4(vL, vE, vI, vT));
        }
        size_t base = base_bt + (size_t)t4;
        st_cs4(o0 + base, make_float4(a0[0], a0[1], a0[2], a0[3]));
        st_cs4(o1 + base, make_float4(a1[0], a1[1], a1[2], a1[3]));
        st_cs4(o2 + base, make_float4(a2[0], a2[1], a2[2], a2[3]));
        st_cs4(o3 + base, make_float4(a3[0], a3[1], a3[2], a3[3]));
    }
}

extern "C" void kernel_launch(void* const* d_in, const int* in_sizes, int n_in,
                              void* d_out, int out_size) {
    const float* input = (const float*)d_in[0];   // [B,T,N] float32
    const float* wts   = (const float*)d_in[1];   // [24] float32
    float* out = (float*)d_out;                   // 12*B*T float32

    // BT/2 warps, 8 warps per 256-thread block
    int warps = BT / 2;                 // 512000
    int blocks = warps / 8;             // 64000
    rowsum_kernel<<<blocks, 256>>>(input);

    // one thread per batch element; 32-thread blocks to spread 64 warps wide
    scan_kernel<<<BATCH / 32, 32>>>(wts, out);
}